// round 6
// baseline (speedup 1.0000x reference)
#include <cuda_runtime.h>
#include <math.h>

// Problem constants (hardcoded in reference)
#define B 32
#define D 128
#define K 512
#define C 10
#define KH (K / 2)        // 256 k-cols per half
#define NT 512
#define NG 8              // d-groups
#define DCH (D / NG)      // 16 d-rows per group

// Cross-CTA state
__device__ float g_fac2[2][C][KH];     // fac2 halves
__device__ float g_hpart[B][2][C];     // per (row, half) partial h
__device__ int   g_ready[2] = {0, 0};  // producers done per half (target C)
__device__ int   g_rowcnt[B] = {0};    // halves done per row (target 2)
__device__ int   g_done = 0;           // finalizers done (target B)

__device__ __forceinline__ int ld_acquire_gpu(const int* p) {
    int v;
    asm volatile("ld.acquire.gpu.s32 %0, [%1];" : "=r"(v) : "l"(p) : "memory");
    return v;
}
__device__ __forceinline__ void red_release_add(int* p, int v) {
    asm volatile("red.release.gpu.global.add.s32 [%0], %1;" :: "l"(p), "r"(v) : "memory");
}

// 84 CTAs x 512 threads:
//   CTA 0..63  : consumer (b = blk>>1, half = blk&1)
//   CTA 64..83 : producer (c = (blk-64)>>1, half = (blk-64)&1)
__global__ __launch_bounds__(NT, 1) void fused_kernel(
    const float* __restrict__ x,
    const float* __restrict__ mu,
    const float* __restrict__ U,
    const float* __restrict__ V,
    float* __restrict__ out) {
    __shared__ float sx[D];
    __shared__ float part[NG][KH];   // 8 KB d-split partials
    __shared__ float hs[NG][C];
    __shared__ int   sflag;

    const int t  = threadIdx.x;
    const int g  = t >> 6;           // d-group 0..7
    const int tt = t & 63;           // float4 col within the 256-col half

    const bool producer = (blockIdx.x >= 2 * B);
    const int  pid  = producer ? (blockIdx.x - 2 * B) : blockIdx.x;
    const int  row  = pid >> 1;      // b or c
    const int  half = pid & 1;

    const float* src = producer ? (mu + row * D) : (x + row * D);
    const float* W   = producer ? V : U;
    const float* Wg  = W + half * KH + g * DCH * K;

    // ---- prefetch this thread's 16 W rows (front-batched MLP, one exposure)
    float4 w[DCH];
#pragma unroll
    for (int i = 0; i < DCH; i++)
        w[i] = reinterpret_cast<const float4*>(Wg + i * K)[tt];

    if (t < D) sx[t] = src[t];
    __syncthreads();

    // ---- phase 1: factor half-row, 16-d chunk per group ----
    float4 acc = make_float4(0.f, 0.f, 0.f, 0.f);
    const float* sg = sx + g * DCH;
#pragma unroll
    for (int i = 0; i < DCH; i++) {
        const float sv = sg[i];
        acc.x = fmaf(sv, w[i].x, acc.x);
        acc.y = fmaf(sv, w[i].y, acc.y);
        acc.z = fmaf(sv, w[i].z, acc.z);
        acc.w = fmaf(sv, w[i].w, acc.w);
    }
    reinterpret_cast<float4*>(&part[g][tt * 4])[0] = acc;
    __syncthreads();

    if (producer) {
        // reduce 8 d-partials, publish fac2[half][c]
        if (t < 64) {
            float4 r = make_float4(0.f, 0.f, 0.f, 0.f);
#pragma unroll
            for (int gg = 0; gg < NG; gg++) {
                float4 a = reinterpret_cast<const float4*>(&part[gg][t * 4])[0];
                r.x += a.x; r.y += a.y; r.z += a.z; r.w += a.w;
            }
            reinterpret_cast<float4*>(&g_fac2[half][0][0] + row * KH)[t] = r;
        }
        __syncthreads();
        if (t == 0) red_release_add(&g_ready[half], 1);
        return;
    }

    // ---- consumer: wait for this half's 10 fac2 rows ----
    if (t == 0) {
        while (ld_acquire_gpu(&g_ready[half]) < C) { }
    }
    __syncthreads();

    // ---- phase 2: thread t<256 owns k = t ----
    float p[C];
    if (t < KH) {
        float f1 = 0.f;
#pragma unroll
        for (int gg = 0; gg < NG; gg++) f1 += part[gg][t];
#pragma unroll
        for (int c = 0; c < C; c++)
            p[c] = f1 * g_fac2[half][c][t];
    } else {
#pragma unroll
        for (int c = 0; c < C; c++) p[c] = 0.f;
    }

#pragma unroll
    for (int o = 16; o > 0; o >>= 1) {
#pragma unroll
        for (int c = 0; c < C; c++)
            p[c] += __shfl_xor_sync(0xffffffffu, p[c], o);
    }
    const int wrp  = t >> 5;
    const int lane = t & 31;
    if (lane == 0 && wrp < NG) {
#pragma unroll
        for (int c = 0; c < C; c++) hs[wrp][c] = p[c];
    }
    __syncthreads();

    // publish this half's partial h row, detect last-of-2
    if (t < C) {
        float h = 0.f;
#pragma unroll
        for (int w2 = 0; w2 < NG; w2++) h += hs[w2][t];
        g_hpart[row][half][t] = h;
    }
    __threadfence();
    __syncthreads();
    if (t == 0) {
        sflag = (atomicAdd(&g_rowcnt[row], 1) == 1);
    }
    __syncthreads();
    if (!sflag) return;

    // ---- finale for row b (runs in exactly one CTA per row, in parallel) ----
    __threadfence();  // acquire: order hpart reads after counter observation
    if (t == 0) {
        float h[C];
        float m = -INFINITY;
#pragma unroll
        for (int c = 0; c < C; c++) {
            h[c] = g_hpart[row][0][c] + g_hpart[row][1][c];
            m = fmaxf(m, h[c]);
        }
        float se = 0.f;
#pragma unroll
        for (int c = 0; c < C; c++) se += expf(h[c] - m);
        const float lse = m + logf(se);
#pragma unroll
        for (int c = 0; c < C; c++) out[row * C + c] = h[c] - lse;

        // last finalizer resets all counters for the next graph replay
        if (atomicAdd(&g_done, 1) == B - 1) {
#pragma unroll
            for (int b2 = 0; b2 < B; b2++) g_rowcnt[b2] = 0;
            g_ready[0] = 0;
            g_ready[1] = 0;
            g_done = 0;
        }
    }
}

extern "C" void kernel_launch(void* const* d_in, const int* in_sizes, int n_in,
                              void* d_out, int out_size) {
    const float* x  = (const float*)d_in[0];  // [32, 128]
    const float* mu = (const float*)d_in[1];  // [10, 128]
    const float* U  = (const float*)d_in[2];  // [128, 512]
    const float* V  = (const float*)d_in[3];  // [128, 512]
    float* out = (float*)d_out;               // [32, 10]

    fused_kernel<<<2 * B + 2 * C, NT>>>(x, mu, U, V, out);
}

// round 7
// speedup vs baseline: 1.0208x; 1.0208x over previous
#include <cuda_runtime.h>
#include <math.h>

// Problem constants (hardcoded in reference)
#define B 32
#define D 128
#define K 512
#define C 10
#define KH (K / 2)
#define NT 1024
#define NFLAG 20          // (c, half) producer flags

// Cross-CTA state
__device__ float g_fac2[C][K];
__device__ int   g_flag[NFLAG];   // one release-flag per producer CTA
__device__ int   g_done = 0;      // consumers done (target B)

__device__ __forceinline__ void st_release_gpu(int* p, int v) {
    asm volatile("st.release.gpu.global.s32 [%0], %1;" :: "l"(p), "r"(v) : "memory");
}
__device__ __forceinline__ int4 ld_volatile_v4(const int4* p) {
    int4 v;
    asm volatile("ld.volatile.global.v4.s32 {%0,%1,%2,%3}, [%4];"
                 : "=r"(v.x), "=r"(v.y), "=r"(v.z), "=r"(v.w) : "l"(p) : "memory");
    return v;
}
__device__ __forceinline__ void fence_acq_rel_gpu() {
    asm volatile("fence.acq_rel.gpu;" ::: "memory");
}

// 52 CTAs x 1024 threads:
//   CTA 0..31  : consumer b — full-K fac1 row in smem partials, poll flags,
//                dot + log_softmax, write out[b].
//   CTA 32..51 : producer (c, half) — half fac2 row (8 loads/thread), publish
//                row slice + release flag. Finishes ~1 exposure before consumers.
__global__ __launch_bounds__(NT, 1) void fused_kernel(
    const float* __restrict__ x,
    const float* __restrict__ mu,
    const float* __restrict__ U,
    const float* __restrict__ V,
    float* __restrict__ out) {
    __shared__ float sx[D];
    __shared__ float part[8][K];     // consumer: 8 d-groups x 512 (16 KB)
    __shared__ float f1s[K];
    __shared__ float hrow[C];
    // producer view of the same 16 KB: 16 d-groups x 256 cols
    float (*part2)[KH] = reinterpret_cast<float (*)[KH]>(&part[0][0]);

    const int t    = threadIdx.x;
    const int w    = t >> 5;
    const int lane = t & 31;

    if (blockIdx.x >= B) {
        // ---------------- producer: fac2 row c, half ----------------
        const int pid  = blockIdx.x - B;
        const int c    = pid >> 1;
        const int half = pid & 1;

        if (t < D) sx[t] = mu[c * D + t];
        __syncthreads();

        const int g  = t >> 6;       // d-group 0..15 (8 d-rows each)
        const int tt = t & 63;       // float4 col within half
        const float* Vg = V + half * KH + g * 8 * K;

        float4 wv[8];
#pragma unroll
        for (int i = 0; i < 8; i++)
            wv[i] = reinterpret_cast<const float4*>(Vg + i * K)[tt];

        float4 acc = make_float4(0.f, 0.f, 0.f, 0.f);
        const float* sg = sx + g * 8;
#pragma unroll
        for (int i = 0; i < 8; i++) {
            const float sv = sg[i];
            acc.x = fmaf(sv, wv[i].x, acc.x);
            acc.y = fmaf(sv, wv[i].y, acc.y);
            acc.z = fmaf(sv, wv[i].z, acc.z);
            acc.w = fmaf(sv, wv[i].w, acc.w);
        }
        reinterpret_cast<float4*>(&part2[g][tt * 4])[0] = acc;
        __syncthreads();

        if (t < 64) {
            float4 r = make_float4(0.f, 0.f, 0.f, 0.f);
#pragma unroll
            for (int gg = 0; gg < 16; gg++) {
                float4 a = reinterpret_cast<const float4*>(&part2[gg][t * 4])[0];
                r.x += a.x; r.y += a.y; r.z += a.z; r.w += a.w;
            }
            reinterpret_cast<float4*>(&g_fac2[c][half * KH])[t] = r;
        }
        __syncthreads();                    // all slice stores happen-before flag
        if (t == 0) st_release_gpu(&g_flag[pid], 1);
        return;
    }

    // ---------------- consumer: output row b ----------------
    const int row = blockIdx.x;
    if (t < D) sx[t] = x[row * D + t];
    __syncthreads();

    const int g  = t >> 7;           // d-group 0..7 (16 d-rows each)
    const int tt = t & 127;          // float4 col, full K
    const float* Ug = U + g * 16 * K;
    const float* sg = sx + g * 16;

    float4 acc = make_float4(0.f, 0.f, 0.f, 0.f);
#pragma unroll
    for (int i = 0; i < 16; i++) {
        float4 wv = reinterpret_cast<const float4*>(Ug + i * K)[tt];
        const float sv = sg[i];
        acc.x = fmaf(sv, wv.x, acc.x);
        acc.y = fmaf(sv, wv.y, acc.y);
        acc.z = fmaf(sv, wv.z, acc.z);
        acc.w = fmaf(sv, wv.w, acc.w);
    }
    reinterpret_cast<float4*>(&part[g][tt * 4])[0] = acc;

    // poll the 20 flags (expected already set — producers are lighter)
    if (t == 0) {
        const int4* fp = reinterpret_cast<const int4*>(g_flag);
        for (;;) {
            int s = 0;
#pragma unroll
            for (int j = 0; j < NFLAG / 4; j++) {
                int4 f = ld_volatile_v4(fp + j);
                s += f.x + f.y + f.z + f.w;
            }
            if (s == NFLAG) break;
        }
        fence_acq_rel_gpu();
    }
    __syncthreads();   // part[] ready AND flags observed

    // fold d-group partials: f1s[k]
    if (t < K) {
        float f = part[0][t];
#pragma unroll
        for (int gg = 1; gg < 8; gg++) f += part[gg][t];
        f1s[t] = f;
    }
    __syncthreads();

    // one warp per class: dot(f1s, fac2[c]) over K=512 (4 float4 per lane)
    if (w < C) {
        float p = 0.f;
#pragma unroll
        for (int j = 0; j < 4; j++) {
            const int i4 = lane + j * 32;
            float4 a = reinterpret_cast<const float4*>(f1s)[i4];
            float4 b2 = reinterpret_cast<const float4*>(&g_fac2[w][0])[i4];
            p += a.x * b2.x + a.y * b2.y + a.z * b2.z + a.w * b2.w;
        }
#pragma unroll
        for (int o = 16; o > 0; o >>= 1)
            p += __shfl_xor_sync(0xffffffffu, p, o);
        if (lane == 0) hrow[w] = p;
    }
    __syncthreads();

    if (t == 0) {
        float h[C];
        float m = -INFINITY;
#pragma unroll
        for (int c = 0; c < C; c++) { h[c] = hrow[c]; m = fmaxf(m, h[c]); }
        float se = 0.f;
#pragma unroll
        for (int c = 0; c < C; c++) se += expf(h[c] - m);
        const float lse = m + logf(se);
#pragma unroll
        for (int c = 0; c < C; c++) out[row * C + c] = h[c] - lse;

        // last consumer resets flags for the next graph replay
        if (atomicAdd(&g_done, 1) == B - 1) {
#pragma unroll
            for (int j = 0; j < NFLAG; j++) g_flag[j] = 0;
            g_done = 0;
        }
    }
}

extern "C" void kernel_launch(void* const* d_in, const int* in_sizes, int n_in,
                              void* d_out, int out_size) {
    const float* x  = (const float*)d_in[0];  // [32, 128]
    const float* mu = (const float*)d_in[1];  // [10, 128]
    const float* U  = (const float*)d_in[2];  // [128, 512]
    const float* V  = (const float*)d_in[3];  // [128, 512]
    float* out = (float*)d_out;               // [32, 10]

    fused_kernel<<<B + NFLAG, NT>>>(x, mu, U, V, out);
}